// round 15
// baseline (speedup 1.0000x reference)
#include <cuda_runtime.h>
#include <cuda_fp16.h>
#include <math.h>
#include <stdint.h>

// Problem constants
constexpr int Bb = 2;
constexpr int Tt = 2048;
constexpr int Cc = 1024;
constexpr int Hh = 16;
constexpr int Dd = 64;
constexpr int Mrows = Bb * Tt;        // 4096
constexpr int C3 = 3 * Cc;            // 3072
constexpr int BH = Bb * Hh;           // 32
constexpr int NQT = Tt / 128;         // 16

// Device scratch
__device__ __half g_qkvh[(size_t)Mrows * C3];    // q,k,v fp16
__device__ __half g_attnvh[(size_t)Mrows * Cc];  // attn@V fp16
__device__ __half g_xh[(size_t)Mrows * Cc];      // x fp16
__device__ __half g_wqkvTh[(size_t)C3 * Cc];     // w_qkv^T fp16
__device__ __half g_woTh[(size_t)Cc * Cc];       // w_o^T fp16
__device__ __half g_Eh[(size_t)BH * Tt * Tt];    // E = exp(s - m_tile), fp16
__device__ float g_tilestats[(size_t)BH * Tt * 16 * 2]; // (max, expsum) per (row, ktile)

// ---------------------------------------------------------------------------
// helpers
// ---------------------------------------------------------------------------
__device__ __forceinline__ uint32_t packh2(float a, float b) {
    __half2 h = __floats2half2_rn(a, b);
    return *(uint32_t*)&h;
}
__device__ __forceinline__ uint32_t hmul2u(uint32_t a, uint32_t f) {
    __half2 r = __hmul2(*(__half2*)&a, *(__half2*)&f);
    return *(uint32_t*)&r;
}
__device__ __forceinline__ void mma16h(float* c, const uint32_t* a, const uint32_t* b) {
    asm volatile(
        "mma.sync.aligned.m16n8k16.row.col.f32.f16.f16.f32 "
        "{%0,%1,%2,%3},{%4,%5,%6,%7},{%8,%9},{%0,%1,%2,%3};"
        : "+f"(c[0]), "+f"(c[1]), "+f"(c[2]), "+f"(c[3])
        : "r"(a[0]), "r"(a[1]), "r"(a[2]), "r"(a[3]), "r"(b[0]), "r"(b[1]));
}
__device__ __forceinline__ void ldsm4(uint32_t* r, uint32_t addr) {
    asm volatile("ldmatrix.sync.aligned.m8n8.x4.shared.b16 {%0,%1,%2,%3}, [%4];"
                 : "=r"(r[0]), "=r"(r[1]), "=r"(r[2]), "=r"(r[3]) : "r"(addr));
}
__device__ __forceinline__ void ldsm4t(uint32_t* r, uint32_t addr) {
    asm volatile("ldmatrix.sync.aligned.m8n8.x4.trans.shared.b16 {%0,%1,%2,%3}, [%4];"
                 : "=r"(r[0]), "=r"(r[1]), "=r"(r[2]), "=r"(r[3]) : "r"(addr));
}
__device__ __forceinline__ void cpasync16(uint32_t saddr, const void* gptr) {
    asm volatile("cp.async.ca.shared.global [%0], [%1], 16;\n" ::"r"(saddr), "l"(gptr));
}

// ---------------------------------------------------------------------------
// Prep: x -> fp16; weights -> transposed fp16.
// ---------------------------------------------------------------------------
__global__ __launch_bounds__(256) void convert_x_h(const float* __restrict__ x)
{
    const size_t i = ((size_t)blockIdx.x * 256 + threadIdx.x) * 8;
    float4 v0 = *(const float4*)(x + i);
    float4 v1 = *(const float4*)(x + i + 4);
    uint4 o;
    o.x = packh2(v0.x, v0.y);
    o.y = packh2(v0.z, v0.w);
    o.z = packh2(v1.x, v1.y);
    o.w = packh2(v1.z, v1.w);
    *(uint4*)(g_xh + i) = o;
}

__global__ __launch_bounds__(256) void transpose_h(
    const float* __restrict__ in, __half* __restrict__ out, int N, int K)
{
    __shared__ float t[32][33];
    const int tx = threadIdx.x & 31, ty = threadIdx.x >> 5;
    const int n0 = blockIdx.x * 32, k0 = blockIdx.y * 32;
#pragma unroll
    for (int j = 0; j < 4; j++) {
        int r = ty + j * 8;
        t[r][tx] = in[(size_t)(k0 + r) * N + n0 + tx];
    }
    __syncthreads();
#pragma unroll
    for (int j = 0; j < 4; j++) {
        int r = ty + j * 8;
        out[(size_t)(n0 + r) * K + k0 + tx] = __float2half(t[tx][r]);
    }
}

// ---------------------------------------------------------------------------
// Dense GEMM: C[M,N] = A[M,K] @ BT[N,K]^T + bias[N]   (fp16 HMMA m16n8k16)
// BK=64, 3-stage cp.async pipeline with EAGER issue (loads for tile j+2 are
// launched before computing tile j). Tiles [128][72] halves, stride 144 B.
// 8 warps (2m x 4n), warp tile 64x32.
// ---------------------------------------------------------------------------
template <bool OUT_HALF>
__global__ __launch_bounds__(256, 2) void gemm_h(
    const __half* __restrict__ A, int lda,
    const __half* __restrict__ BT, int ldb,
    const float* __restrict__ bias,
    void* __restrict__ Cv, int ldc, int Kd)
{
    extern __shared__ __half sh[];
    constexpr int STG_B = 36864;          // bytes/stage: A 18432 + B 18432

    const int tid = threadIdx.x;
    const int wid = tid >> 5, lane = tid & 31;
    const int warp_m = wid & 1, warp_n = wid >> 1;
    const int row0 = blockIdx.y * 128;
    const int col0 = blockIdx.x * 128;
    const uint32_t shb = (uint32_t)__cvta_generic_to_shared(sh);

    const int arow = (lane & 7) + ((lane >> 3) & 1) * 8;
    const int ahalf = lane >> 4;
    const int brow = (lane & 7) + (lane >> 4) * 8;
    const int bhalf = (lane >> 3) & 1;

    auto issue = [&](int kt) {
        const int s = kt % 3, k0 = kt * 64;
#pragma unroll
        for (int i = 0; i < 4; i++) {
            int c = tid + i * 256, r = c >> 3, ch = c & 7;
            cpasync16(shb + s * STG_B + r * 144 + ch * 16,
                      A + (size_t)(row0 + r) * lda + k0 + ch * 8);
        }
#pragma unroll
        for (int i = 0; i < 4; i++) {
            int c = tid + i * 256, r = c >> 3, ch = c & 7;
            cpasync16(shb + s * STG_B + 18432 + r * 144 + ch * 16,
                      BT + (size_t)(col0 + r) * ldb + k0 + ch * 8);
        }
        asm volatile("cp.async.commit_group;");
    };

    const int nt = Kd / 64;
    issue(0);
    issue(1);

    float acc[4][4][4] = {};

    for (int j = 0; j < nt; j++) {
        if (j == nt - 1) {
            asm volatile("cp.async.wait_group 0;");
        } else {
            asm volatile("cp.async.wait_group 1;");
        }
        __syncthreads();
        // EAGER issue: stage (j+2)%3 was fully consumed at iter j-1.
        if (j + 2 < nt) issue(j + 2);

        const int s = j % 3;
        const uint32_t ab = shb + s * STG_B;
        const uint32_t bb = ab + 18432;
#pragma unroll
        for (int ks = 0; ks < 64; ks += 16) {
            uint32_t af[4][4], bf[2][4];
#pragma unroll
            for (int mi = 0; mi < 4; mi++)
                ldsm4(af[mi], ab + (warp_m * 64 + mi * 16 + arow) * 144 + (ks + ahalf * 8) * 2);
#pragma unroll
            for (int np = 0; np < 2; np++)
                ldsm4(bf[np], bb + (warp_n * 32 + np * 16 + brow) * 144 + (ks + bhalf * 8) * 2);
#pragma unroll
            for (int mi = 0; mi < 4; mi++)
#pragma unroll
                for (int np = 0; np < 2; np++) {
                    mma16h(acc[mi][np * 2 + 0], af[mi], &bf[np][0]);
                    mma16h(acc[mi][np * 2 + 1], af[mi], &bf[np][2]);
                }
        }
    }

    const int g2 = lane >> 2, tg2 = lane & 3;
#pragma unroll
    for (int mi = 0; mi < 4; mi++) {
#pragma unroll
        for (int ni = 0; ni < 4; ni++) {
            int m = row0 + warp_m * 64 + mi * 16 + g2;
            int n = col0 + warp_n * 32 + ni * 8 + tg2 * 2;
            float v00 = acc[mi][ni][0] + bias[n], v01 = acc[mi][ni][1] + bias[n + 1];
            float v10 = acc[mi][ni][2] + bias[n], v11 = acc[mi][ni][3] + bias[n + 1];
            if (OUT_HALF) {
                __half* Cm = (__half*)Cv;
                *(uint32_t*)(Cm + (size_t)m * ldc + n) = packh2(v00, v01);
                *(uint32_t*)(Cm + (size_t)(m + 8) * ldc + n) = packh2(v10, v11);
            } else {
                float* Cm = (float*)Cv;
                *(float2*)(Cm + (size_t)m * ldc + n) = {v00, v01};
                *(float2*)(Cm + (size_t)(m + 8) * ldc + n) = {v10, v11};
            }
        }
    }
}

// ---------------------------------------------------------------------------
// Scores: E = exp(scale*QK^T - tile_rowmax) -> g_Eh (fp16), stats -> gmem.
// Upper tiles: final zeros into attn_w. (round-14 proven)
// ---------------------------------------------------------------------------
__global__ __launch_bounds__(256, 2) void scores_h(float* __restrict__ S)
{
    const int bh = blockIdx.z;
    const int q0 = blockIdx.y * 128;
    const int k0t = blockIdx.x * 128;
    const int tid = threadIdx.x;

    if (blockIdx.x > blockIdx.y) {
        float* Sb = S + (size_t)bh * Tt * Tt;
        const float4 z = {0.f, 0.f, 0.f, 0.f};
#pragma unroll
        for (int i = 0; i < 16; i++) {
            int f = i * 256 + tid;
            int r = f >> 5, c = (f & 31) * 4;
            *(float4*)(Sb + (size_t)(q0 + r) * Tt + k0t + c) = z;
        }
        return;
    }

    extern __shared__ __half smh[];
    __half* Qs = smh;                 // [128][72]
    __half* Ks = smh + 128 * 72;      // [128][72]
    __shared__ float sred[128][4];
    __shared__ float sredm[128];

    const int b = bh / Hh, h = bh % Hh;
    const int wid = tid >> 5, lane = tid & 31;
    const int g = lane >> 2, tg = lane & 3;
    const int warp_m = wid & 1, warp_n = wid >> 1;

    const int arow = (lane & 7) + ((lane >> 3) & 1) * 8;
    const int ahalf = lane >> 4;
    const int brow = (lane & 7) + (lane >> 4) * 8;
    const int bhalf = (lane >> 3) & 1;

    const __half* Qb = g_qkvh + (size_t)(b * Tt + q0) * C3 + h * Dd;
    const __half* Kb = g_qkvh + (size_t)(b * Tt + k0t) * C3 + Cc + h * Dd;
    const uint32_t qsb = (uint32_t)__cvta_generic_to_shared(Qs);
    const uint32_t ksb = (uint32_t)__cvta_generic_to_shared(Ks);

#pragma unroll
    for (int i = 0; i < 4; i++) {
        int c = tid + i * 256, r = c >> 3, ch = c & 7;
        cpasync16(qsb + r * 144 + ch * 16, Qb + (size_t)r * C3 + ch * 8);
    }
#pragma unroll
    for (int i = 0; i < 4; i++) {
        int c = tid + i * 256, r = c >> 3, ch = c & 7;
        cpasync16(ksb + r * 144 + ch * 16, Kb + (size_t)r * C3 + ch * 8);
    }
    asm volatile("cp.async.commit_group;");
    asm volatile("cp.async.wait_group 0;");
    __syncthreads();

    float acc[4][4][4] = {};
#pragma unroll
    for (int ks = 0; ks < 64; ks += 16) {
        uint32_t af[4][4], bf[2][4];
#pragma unroll
        for (int mi = 0; mi < 4; mi++)
            ldsm4(af[mi], qsb + (warp_m * 64 + mi * 16 + arow) * 144 + (ks + ahalf * 8) * 2);
#pragma unroll
        for (int np = 0; np < 2; np++)
            ldsm4(bf[np], ksb + (warp_n * 32 + np * 16 + brow) * 144 + (ks + bhalf * 8) * 2);
#pragma unroll
        for (int mi = 0; mi < 4; mi++)
#pragma unroll
            for (int np = 0; np < 2; np++) {
                mma16h(acc[mi][np * 2 + 0], af[mi], &bf[np][0]);
                mma16h(acc[mi][np * 2 + 1], af[mi], &bf[np][2]);
            }
    }

    // scale + diag mask
    const float scale = 0.125f;
    const bool diag = (blockIdx.x == blockIdx.y);
    const float NEG = -INFINITY;
#pragma unroll
    for (int mi = 0; mi < 4; mi++) {
        int r0 = warp_m * 64 + mi * 16 + g;
#pragma unroll
        for (int ni = 0; ni < 4; ni++) {
            int n0 = warp_n * 32 + ni * 8 + tg * 2;
            float* a = acc[mi][ni];
            a[0] *= scale; a[1] *= scale; a[2] *= scale; a[3] *= scale;
            if (diag) {
                if (n0 > r0)     a[0] = NEG;
                if (n0 + 1 > r0) a[1] = NEG;
                if (n0 > r0 + 8)     a[2] = NEG;
                if (n0 + 1 > r0 + 8) a[3] = NEG;
            }
        }
    }

    // tile rowmax
    float mx[4][2];
#pragma unroll
    for (int mi = 0; mi < 4; mi++) {
        float m0 = -INFINITY, m1 = -INFINITY;
#pragma unroll
        for (int ni = 0; ni < 4; ni++) {
            m0 = fmaxf(m0, fmaxf(acc[mi][ni][0], acc[mi][ni][1]));
            m1 = fmaxf(m1, fmaxf(acc[mi][ni][2], acc[mi][ni][3]));
        }
        m0 = fmaxf(m0, __shfl_xor_sync(0xffffffffu, m0, 1));
        m0 = fmaxf(m0, __shfl_xor_sync(0xffffffffu, m0, 2));
        m1 = fmaxf(m1, __shfl_xor_sync(0xffffffffu, m1, 1));
        m1 = fmaxf(m1, __shfl_xor_sync(0xffffffffu, m1, 2));
        mx[mi][0] = m0; mx[mi][1] = m1;
    }
    if (tg == 0) {
#pragma unroll
        for (int mi = 0; mi < 4; mi++) {
            sred[warp_m * 64 + mi * 16 + g][warp_n] = mx[mi][0];
            sred[warp_m * 64 + mi * 16 + g + 8][warp_n] = mx[mi][1];
        }
    }
    __syncthreads();
    if (tid < 128) {
        sredm[tid] = fmaxf(fmaxf(sred[tid][0], sred[tid][1]),
                           fmaxf(sred[tid][2], sred[tid][3]));
    }
    __syncthreads();

    // E = exp(a - rowmax); write E fp16; accumulate sums
    __half* Eb = g_Eh + (size_t)bh * Tt * Tt;
#pragma unroll
    for (int mi = 0; mi < 4; mi++) {
        int r0 = warp_m * 64 + mi * 16 + g;
        float rm0 = sredm[r0];
        float rm1 = sredm[r0 + 8];
        float s0 = 0.f, s1 = 0.f;
#pragma unroll
        for (int ni = 0; ni < 4; ni++) {
            float* a = acc[mi][ni];
            a[0] = __expf(a[0] - rm0);
            a[1] = __expf(a[1] - rm0);
            a[2] = __expf(a[2] - rm1);
            a[3] = __expf(a[3] - rm1);
            s0 += a[0] + a[1];
            s1 += a[2] + a[3];
            int n0 = warp_n * 32 + ni * 8 + tg * 2;
            *(uint32_t*)(Eb + (size_t)(q0 + r0) * Tt + k0t + n0) = packh2(a[0], a[1]);
            *(uint32_t*)(Eb + (size_t)(q0 + r0 + 8) * Tt + k0t + n0) = packh2(a[2], a[3]);
        }
        s0 += __shfl_xor_sync(0xffffffffu, s0, 1);
        s0 += __shfl_xor_sync(0xffffffffu, s0, 2);
        s1 += __shfl_xor_sync(0xffffffffu, s1, 1);
        s1 += __shfl_xor_sync(0xffffffffu, s1, 2);
        mx[mi][0] = s0; mx[mi][1] = s1;
    }
    __syncthreads();
    if (tg == 0) {
#pragma unroll
        for (int mi = 0; mi < 4; mi++) {
            sred[warp_m * 64 + mi * 16 + g][warp_n] = mx[mi][0];
            sred[warp_m * 64 + mi * 16 + g + 8][warp_n] = mx[mi][1];
        }
    }
    __syncthreads();
    if (tid < 128) {
        float s4 = sred[tid][0] + sred[tid][1] + sred[tid][2] + sred[tid][3];
        size_t idx = (((size_t)bh * Tt + q0 + tid) * 16 + (k0t >> 7)) * 2;
        g_tilestats[idx] = sredm[tid];
        g_tilestats[idx + 1] = s4;
    }
}

// ---------------------------------------------------------------------------
// PV (round-14 proven): prologue combines tile stats -> f[row][kt];
// cp.async E+V fp16, hmul2-scaled A-frags, mma; write final P fp32 to attn_w.
// ---------------------------------------------------------------------------
__global__ __launch_bounds__(256, 2) void pv_h(float* __restrict__ S)
{
    __shared__ __half Es[2][128 * 40];
    __shared__ __half Vs[2][32 * 72];
    __shared__ float fct[128][17];

    const int qt = (NQT - 1) - blockIdx.x;   // heavy tiles first
    const int q0 = qt * 128;
    const int bh = blockIdx.y;
    const int b = bh / Hh, h = bh % Hh;
    const int tid = threadIdx.x, wid = tid >> 5, lane = tid & 31;
    const int g = lane >> 2, tg = lane & 3;
    const int warp_m = wid >> 1, warp_n = wid & 1;
    const int nkt = qt + 1;

    if (tid < 128) {
        const float* st = g_tilestats + ((size_t)bh * Tt + q0 + tid) * 32;
        float m = -INFINITY;
        for (int kt = 0; kt < nkt; kt++) m = fmaxf(m, st[kt * 2]);
        float l = 0.f;
        for (int kt = 0; kt < nkt; kt++) l += st[kt * 2 + 1] * __expf(st[kt * 2] - m);
        const float inv = 1.0f / l;
        for (int kt = 0; kt < nkt; kt++) fct[tid][kt] = __expf(st[kt * 2] - m) * inv;
    }

    float* Sb = S + (size_t)bh * Tt * Tt + (size_t)q0 * Tt;
    const __half* Ebg = g_Eh + (size_t)bh * Tt * Tt + (size_t)q0 * Tt;
    const __half* Vb = g_qkvh + (size_t)(b * Tt) * C3 + 2 * Cc + h * Dd;

    const uint32_t esb = (uint32_t)__cvta_generic_to_shared(Es);
    const uint32_t vsb = (uint32_t)__cvta_generic_to_shared(Vs);

    const int arow = (lane & 7) + ((lane >> 3) & 1) * 8;
    const int ahalf = lane >> 4;
    const int krow = (lane & 7) + ((lane >> 3) & 1) * 8;
    const int nhalf = (lane >> 4) * 8;

    auto issue = [&](int j) {
        const int s = j & 1, k0 = j * 32;
        const uint32_t eb = esb + (uint32_t)(s * 128 * 40 * 2);
#pragma unroll
        for (int i = 0; i < 2; i++) {
            int c = tid + i * 256, r = c >> 2, ch = c & 3;
            cpasync16(eb + r * 80 + ch * 16, Ebg + (size_t)r * Tt + k0 + ch * 8);
        }
        const uint32_t vb = vsb + (uint32_t)(s * 32 * 72 * 2);
        {
            int r = tid >> 3, ch = tid & 7;
            cpasync16(vb + r * 144 + ch * 16, Vb + (size_t)(k0 + r) * C3 + ch * 8);
        }
        asm volatile("cp.async.commit_group;");
    };

    const int nIter = nkt * 4;
    issue(0);

    float acc[2][4][4] = {};
    for (int j = 0; j < nIter; j++) {
        if (j + 1 < nIter) {
            issue(j + 1);
            asm volatile("cp.async.wait_group 1;");
        } else {
            asm volatile("cp.async.wait_group 0;");
        }
        __syncthreads();

        const int s = j & 1;
        const int kt = j >> 2;
        const uint32_t ejb = esb + (uint32_t)(s * 128 * 40 * 2);
        const uint32_t vjb = vsb + (uint32_t)(s * 32 * 72 * 2);

        uint32_t fh[2][2];
#pragma unroll
        for (int mi = 0; mi < 2; mi++) {
            int m = warp_m * 32 + mi * 16;
            __half2 t0 = __float2half2_rn(fct[m + g][kt]);
            __half2 t1 = __float2half2_rn(fct[m + g + 8][kt]);
            fh[mi][0] = *(uint32_t*)&t0;
            fh[mi][1] = *(uint32_t*)&t1;
        }

#pragma unroll
        for (int ks = 0; ks < 32; ks += 16) {
            uint32_t af[2][4], bf[2][4];
#pragma unroll
            for (int mi = 0; mi < 2; mi++) {
                ldsm4(af[mi], ejb + (warp_m * 32 + mi * 16 + arow) * 80 + (ks + ahalf * 8) * 2);
                af[mi][0] = hmul2u(af[mi][0], fh[mi][0]);
                af[mi][2] = hmul2u(af[mi][2], fh[mi][0]);
                af[mi][1] = hmul2u(af[mi][1], fh[mi][1]);
                af[mi][3] = hmul2u(af[mi][3], fh[mi][1]);
            }
#pragma unroll
            for (int np = 0; np < 2; np++)
                ldsm4t(bf[np], vjb + (ks + krow) * 144 + (warp_n * 32 + np * 16 + nhalf) * 2);
#pragma unroll
            for (int mi = 0; mi < 2; mi++)
#pragma unroll
                for (int np = 0; np < 2; np++) {
                    mma16h(acc[mi][np * 2 + 0], af[mi], &bf[np][0]);
                    mma16h(acc[mi][np * 2 + 1], af[mi], &bf[np][2]);
                }
        }

        {
            const int r = tid >> 1, c0 = (tid & 1) * 16;
            const float f = fct[r][kt];
            const __half* Er = Es[s] + r * 40 + c0;
            float* dst = Sb + (size_t)r * Tt + j * 32 + c0;
#pragma unroll
            for (int q2 = 0; q2 < 2; q2++) {
                uint4 u = *(const uint4*)(Er + q2 * 8);
                float2 e0 = __half22float2(*(__half2*)&u.x);
                float2 e1 = __half22float2(*(__half2*)&u.y);
                float2 e2 = __half22float2(*(__half2*)&u.z);
                float2 e3 = __half22float2(*(__half2*)&u.w);
                float4 o0 = {e0.x * f, e0.y * f, e1.x * f, e1.y * f};
                float4 o1 = {e2.x * f, e2.y * f, e3.x * f, e3.y * f};
                *(float4*)(dst + q2 * 8) = o0;
                *(float4*)(dst + q2 * 8 + 4) = o1;
            }
        }
        __syncthreads();
    }

#pragma unroll
    for (int mi = 0; mi < 2; mi++) {
#pragma unroll
        for (int ni = 0; ni < 4; ni++) {
            int q = q0 + warp_m * 32 + mi * 16 + g;
            int n = warp_n * 32 + ni * 8 + tg * 2;
            __half* dst0 = g_attnvh + (size_t)(b * Tt + q) * Cc + h * Dd + n;
            __half* dst1 = g_attnvh + (size_t)(b * Tt + q + 8) * Cc + h * Dd + n;
            *(uint32_t*)dst0 = packh2(acc[mi][ni][0], acc[mi][ni][1]);
            *(uint32_t*)dst1 = packh2(acc[mi][ni][2], acc[mi][ni][3]);
        }
    }
}

// ---------------------------------------------------------------------------
extern "C" void kernel_launch(void* const* d_in, const int* in_sizes, int n_in,
                              void* d_out, int out_size)
{
    const float* x     = (const float*)d_in[0];
    const float* w_qkv = (const float*)d_in[1];
    const float* b_qkv = (const float*)d_in[2];
    const float* w_o   = (const float*)d_in[3];
    const float* b_o   = (const float*)d_in[4];

    float* out   = (float*)d_out;
    float* attnw = out + (size_t)Mrows * Cc;   // [o | attn_w]

    __half *qkvh_ptr = nullptr, *attnvh_ptr = nullptr, *xh_ptr = nullptr;
    __half *wqkvTh_ptr = nullptr, *woTh_ptr = nullptr;
    cudaGetSymbolAddress((void**)&qkvh_ptr,   g_qkvh);
    cudaGetSymbolAddress((void**)&attnvh_ptr, g_attnvh);
    cudaGetSymbolAddress((void**)&xh_ptr,     g_xh);
    cudaGetSymbolAddress((void**)&wqkvTh_ptr, g_wqkvTh);
    cudaGetSymbolAddress((void**)&woTh_ptr,   g_woTh);

    const int gemm_smem   = 3 * 36864;          // 110592
    const int scores_smem = 2 * 128 * 72 * 2;   // 36864
    static bool attr_set = false;
    if (!attr_set) {
        cudaFuncSetAttribute(gemm_h<true>, cudaFuncAttributeMaxDynamicSharedMemorySize,
                             gemm_smem);
        cudaFuncSetAttribute(gemm_h<false>, cudaFuncAttributeMaxDynamicSharedMemorySize,
                             gemm_smem);
        cudaFuncSetAttribute(scores_h, cudaFuncAttributeMaxDynamicSharedMemorySize,
                             scores_smem);
        attr_set = true;
    }

    // 0) prep
    convert_x_h<<<(Mrows * Cc) / (256 * 8), 256>>>(x);
    {
        dim3 gt(C3 / 32, Cc / 32);
        transpose_h<<<gt, 256>>>(w_qkv, wqkvTh_ptr, C3, Cc);
    }
    {
        dim3 gt(Cc / 32, Cc / 32);
        transpose_h<<<gt, 256>>>(w_o, woTh_ptr, Cc, Cc);
    }
    // 1) QKV projection
    {
        dim3 grid(C3 / 128, Mrows / 128);
        gemm_h<true><<<grid, 256, gemm_smem>>>(xh_ptr, Cc, wqkvTh_ptr, Cc, b_qkv,
                                               qkvh_ptr, C3, Cc);
    }
    // 2) Scores -> E fp16 + tile stats (upper tiles -> final zeros in attn_w)
    {
        dim3 grid(Tt / 128, Tt / 128, BH);
        scores_h<<<grid, 256, scores_smem>>>(attnw);
    }
    // 3) P @ V (factors in prologue; writes final attn_w)
    {
        dim3 grid(NQT, BH);
        pv_h<<<grid, 256>>>(attnw);
    }
    // 4) Output projection
    {
        dim3 grid(Cc / 128, Mrows / 128);
        gemm_h<false><<<grid, 256, gemm_smem>>>(attnvh_ptr, Cc, woTh_ptr, Cc, b_o,
                                                out, Cc, Cc);
    }
}